// round 1
// baseline (speedup 1.0000x reference)
#include <cuda_runtime.h>

#define USER_NUM 100000
#define ITEM_NUM 50000
#define N_NODES  150000
#define NNZ      4800000
#define EMB      64
#define EPSV     0.2f
#define NORM_EPS 1e-12f

// Scratch (no allocations allowed): current layer input, spmm output, running sum.
__device__ alignas(256) float g_ego[(size_t)N_NODES * EMB];
__device__ alignas(256) float g_next[(size_t)N_NODES * EMB];
__device__ alignas(256) float g_acc[(size_t)N_NODES * EMB];

// COO SpMM: 16 threads per nonzero, each handles one float4 chunk of the
// 64-wide embedding. Gather is coalesced (256B per nnz), scatter uses
// vectorized global reduction (red.global.add.v4.f32).
__global__ void __launch_bounds__(256)
spmm_kernel(const int* __restrict__ rows, const int* __restrict__ cols,
            const float* __restrict__ vals, const float* __restrict__ x,
            float* __restrict__ y)
{
    long long gtid = (long long)blockIdx.x * blockDim.x + threadIdx.x;
    int e = (int)(gtid >> 4);
    int q = (int)(gtid & 15);
    if (e >= NNZ) return;

    int   c = __ldg(cols + e);
    int   r = __ldg(rows + e);
    float v = __ldg(vals + e);

    float4 t = __ldg(reinterpret_cast<const float4*>(x + (size_t)c * EMB) + q);
    t.x *= v; t.y *= v; t.z *= v; t.w *= v;

    float* dst = y + (size_t)r * EMB + q * 4;
    asm volatile("red.global.add.v4.f32 [%0], {%1, %2, %3, %4};"
                 :: "l"(dst), "f"(t.x), "f"(t.y), "f"(t.z), "f"(t.w)
                 : "memory");
}

// Per-layer epilogue: one warp per node row (2 floats/lane).
//   s      = spmm output for this layer
//   noise  = noise[k] row block
//   ego    = next layer input (s + sign(s)*unit(noise)*eps)
//   acc    = running sum of layer outputs
//   out    = final output, written on k==2 as (acc + ego)/3
__global__ void __launch_bounds__(256)
epi_kernel(const float* __restrict__ s, const float* __restrict__ noise,
           float* __restrict__ ego, float* __restrict__ acc,
           float* __restrict__ out, int k)
{
    int warp = (int)((blockIdx.x * blockDim.x + threadIdx.x) >> 5);
    int lane = threadIdx.x & 31;
    if (warp >= N_NODES) return;

    size_t base = (size_t)warp * EMB + (size_t)lane * 2;

    float2 r = *reinterpret_cast<const float2*>(noise + base);
    float ss = r.x * r.x + r.y * r.y;
    #pragma unroll
    for (int o = 16; o; o >>= 1) ss += __shfl_xor_sync(0xffffffffu, ss, o);
    float nrm   = sqrtf(ss);
    float scale = EPSV / fmaxf(nrm, NORM_EPS);

    float2 sv = *reinterpret_cast<const float2*>(s + base);
    float2 e;
    e.x = sv.x + (sv.x > 0.f ?  scale * r.x : (sv.x < 0.f ? -scale * r.x : 0.f));
    e.y = sv.y + (sv.y > 0.f ?  scale * r.y : (sv.y < 0.f ? -scale * r.y : 0.f));

    if (k < 2) {
        *reinterpret_cast<float2*>(ego + base) = e;
    }
    if (k == 0) {
        *reinterpret_cast<float2*>(acc + base) = e;
    } else if (k == 1) {
        float2 a = *reinterpret_cast<float2*>(acc + base);
        a.x += e.x; a.y += e.y;
        *reinterpret_cast<float2*>(acc + base) = a;
    } else {
        float2 a = *reinterpret_cast<float2*>(acc + base);
        float2 o;
        o.x = (a.x + e.x) * (1.0f / 3.0f);
        o.y = (a.y + e.y) * (1.0f / 3.0f);
        *reinterpret_cast<float2*>(out + base) = o;
    }
}

extern "C" void kernel_launch(void* const* d_in, const int* in_sizes, int n_in,
                              void* d_out, int out_size)
{
    const float* user  = (const float*)d_in[0];
    const float* item  = (const float*)d_in[1];
    const int*   rows  = (const int*)  d_in[2];
    const int*   cols  = (const int*)  d_in[3];
    const float* vals  = (const float*)d_in[4];
    const float* noise = (const float*)d_in[5];
    float*       out   = (float*)d_out;

    float *ego, *nxt, *acc;
    cudaGetSymbolAddress((void**)&ego, g_ego);
    cudaGetSymbolAddress((void**)&nxt, g_next);
    cudaGetSymbolAddress((void**)&acc, g_acc);

    const size_t row_bytes = (size_t)EMB * sizeof(float);

    // ego = concat(user_emb, item_emb)
    cudaMemcpyAsync(ego, user, (size_t)USER_NUM * row_bytes,
                    cudaMemcpyDeviceToDevice);
    cudaMemcpyAsync(ego + (size_t)USER_NUM * EMB, item,
                    (size_t)ITEM_NUM * row_bytes, cudaMemcpyDeviceToDevice);

    const int spmm_blocks = (int)(((long long)NNZ * 16 + 255) / 256);  // 300000
    const int epi_blocks  = (N_NODES + 7) / 8;                          // warp/row

    for (int k = 0; k < 3; k++) {
        cudaMemsetAsync(nxt, 0, (size_t)N_NODES * row_bytes);
        spmm_kernel<<<spmm_blocks, 256>>>(rows, cols, vals, ego, nxt);
        epi_kernel<<<epi_blocks, 256>>>(nxt,
                                        noise + (size_t)k * N_NODES * EMB,
                                        ego, acc, out, k);
    }
}

// round 2
// speedup vs baseline: 2.1528x; 2.1528x over previous
#include <cuda_runtime.h>

#define USER_NUM 100000
#define ITEM_NUM 50000
#define N_NODES  150000
#define NNZ      4800000
#define EMB      64
#define EPSV     0.2f
#define NORM_EPS 1e-12f

#define SCAN_TILE   1024
#define SCAN_BLOCKS ((N_NODES + SCAN_TILE - 1) / SCAN_TILE)  // 147

// ---- scratch (allocation-free) ----
__device__ alignas(16) int   g_cnt[N_NODES];
__device__ alignas(16) int   g_rowptr[N_NODES];
__device__ alignas(16) int   g_woff[N_NODES];
__device__             int   g_bsum[SCAN_BLOCKS];
__device__ alignas(16) int   g_scol[NNZ];
__device__ alignas(16) float g_sval[NNZ];
__device__ alignas(256) float g_e0[(size_t)N_NODES * EMB];
__device__ alignas(256) float g_e1[(size_t)N_NODES * EMB];
__device__ alignas(256) float g_acc[(size_t)N_NODES * EMB];

// ---- counting sort: histogram ----
__global__ void __launch_bounds__(256)
count_kernel(const int* __restrict__ rows)
{
    int i = blockIdx.x * blockDim.x + threadIdx.x;
    if (i < NNZ) atomicAdd(&g_cnt[rows[i]], 1);
}

// ---- scan stage 1: per-block exclusive scan of counts, emit block sums ----
__global__ void __launch_bounds__(256)
scan1_kernel()
{
    __shared__ int sh[256];
    int tid  = threadIdx.x;
    int base = blockIdx.x * SCAN_TILE + tid * 4;

    int v0 = 0, v1 = 0, v2 = 0, v3 = 0;
    if (base + 3 < N_NODES) {
        int4 t = *reinterpret_cast<const int4*>(&g_cnt[base]);
        v0 = t.x; v1 = t.y; v2 = t.z; v3 = t.w;
    } else {
        if (base + 0 < N_NODES) v0 = g_cnt[base + 0];
        if (base + 1 < N_NODES) v1 = g_cnt[base + 1];
        if (base + 2 < N_NODES) v2 = g_cnt[base + 2];
        if (base + 3 < N_NODES) v3 = g_cnt[base + 3];
    }
    int s = v0 + v1 + v2 + v3;
    sh[tid] = s;
    __syncthreads();
    #pragma unroll
    for (int o = 1; o < 256; o <<= 1) {
        int t = (tid >= o) ? sh[tid - o] : 0;
        __syncthreads();
        sh[tid] += t;
        __syncthreads();
    }
    int excl = sh[tid] - s;
    if (base + 0 < N_NODES) g_rowptr[base + 0] = excl;
    excl += v0;
    if (base + 1 < N_NODES) g_rowptr[base + 1] = excl;
    excl += v1;
    if (base + 2 < N_NODES) g_rowptr[base + 2] = excl;
    excl += v2;
    if (base + 3 < N_NODES) g_rowptr[base + 3] = excl;
    if (tid == 255) g_bsum[blockIdx.x] = sh[255];
}

// ---- scan stage 2: single-block exclusive scan of block sums ----
__global__ void __launch_bounds__(256)
scan2_kernel()
{
    __shared__ int sh[256];
    int tid = threadIdx.x;
    int v = (tid < SCAN_BLOCKS) ? g_bsum[tid] : 0;
    sh[tid] = v;
    __syncthreads();
    #pragma unroll
    for (int o = 1; o < 256; o <<= 1) {
        int t = (tid >= o) ? sh[tid - o] : 0;
        __syncthreads();
        sh[tid] += t;
        __syncthreads();
    }
    if (tid < SCAN_BLOCKS) g_bsum[tid] = sh[tid] - v;
}

// ---- scan stage 3: add block offsets; init working offsets ----
__global__ void __launch_bounds__(256)
scan3_kernel()
{
    int i = blockIdx.x * blockDim.x + threadIdx.x;
    if (i < N_NODES) {
        int r = g_rowptr[i] + g_bsum[i / SCAN_TILE];
        g_rowptr[i] = r;
        g_woff[i]   = r;
    }
}

// ---- counting sort: scatter cols/vals into row-sorted order ----
__global__ void __launch_bounds__(256)
scatter_kernel(const int* __restrict__ rows, const int* __restrict__ cols,
               const float* __restrict__ vals)
{
    int i = blockIdx.x * blockDim.x + threadIdx.x;
    if (i < NNZ) {
        int p = atomicAdd(&g_woff[rows[i]], 1);
        g_scol[p] = cols[i];
        g_sval[p] = vals[i];
    }
}

// ---- fused CSR SpMM (warp per row) + sign-perturbation + mean accumulation ----
__global__ void __launch_bounds__(256)
spmm_fused(const float* __restrict__ x, const float* __restrict__ noise,
           float* __restrict__ dst, float* __restrict__ acc,
           float* __restrict__ out, int k)
{
    int warp = (int)((blockIdx.x * (unsigned)blockDim.x + threadIdx.x) >> 5);
    int lane = threadIdx.x & 31;
    if (warp >= N_NODES) return;

    int start = __ldg(&g_rowptr[warp]);
    int end   = (warp + 1 < N_NODES) ? __ldg(&g_rowptr[warp + 1]) : NNZ;

    float sx = 0.f, sy = 0.f;
    int j = start;
    for (; j + 4 <= end; j += 4) {
        int c0 = __ldg(&g_scol[j + 0]);
        int c1 = __ldg(&g_scol[j + 1]);
        int c2 = __ldg(&g_scol[j + 2]);
        int c3 = __ldg(&g_scol[j + 3]);
        float v0 = __ldg(&g_sval[j + 0]);
        float v1 = __ldg(&g_sval[j + 1]);
        float v2 = __ldg(&g_sval[j + 2]);
        float v3 = __ldg(&g_sval[j + 3]);
        float2 a0 = __ldg(reinterpret_cast<const float2*>(x + (size_t)c0 * EMB) + lane);
        float2 a1 = __ldg(reinterpret_cast<const float2*>(x + (size_t)c1 * EMB) + lane);
        float2 a2 = __ldg(reinterpret_cast<const float2*>(x + (size_t)c2 * EMB) + lane);
        float2 a3 = __ldg(reinterpret_cast<const float2*>(x + (size_t)c3 * EMB) + lane);
        sx += v0 * a0.x; sy += v0 * a0.y;
        sx += v1 * a1.x; sy += v1 * a1.y;
        sx += v2 * a2.x; sy += v2 * a2.y;
        sx += v3 * a3.x; sy += v3 * a3.y;
    }
    for (; j < end; j++) {
        int   c = __ldg(&g_scol[j]);
        float v = __ldg(&g_sval[j]);
        float2 a = __ldg(reinterpret_cast<const float2*>(x + (size_t)c * EMB) + lane);
        sx += v * a.x; sy += v * a.y;
    }

    // epilogue: ego = s + sign(s) * l2_normalize(noise_row) * eps
    size_t base = (size_t)warp * EMB + (size_t)lane * 2;
    float2 r = __ldg(reinterpret_cast<const float2*>(noise + base));
    float ss = r.x * r.x + r.y * r.y;
    #pragma unroll
    for (int o = 16; o; o >>= 1) ss += __shfl_xor_sync(0xffffffffu, ss, o);
    float scale = EPSV / fmaxf(sqrtf(ss), NORM_EPS);

    float2 e;
    e.x = sx + (sx > 0.f ? scale * r.x : (sx < 0.f ? -scale * r.x : 0.f));
    e.y = sy + (sy > 0.f ? scale * r.y : (sy < 0.f ? -scale * r.y : 0.f));

    if (k < 2) {
        *reinterpret_cast<float2*>(dst + base) = e;
    }
    if (k == 0) {
        *reinterpret_cast<float2*>(acc + base) = e;
    } else if (k == 1) {
        float2 a = *reinterpret_cast<const float2*>(acc + base);
        a.x += e.x; a.y += e.y;
        *reinterpret_cast<float2*>(acc + base) = a;
    } else {
        float2 a = *reinterpret_cast<const float2*>(acc + base);
        float2 o;
        o.x = (a.x + e.x) * (1.0f / 3.0f);
        o.y = (a.y + e.y) * (1.0f / 3.0f);
        *reinterpret_cast<float2*>(out + base) = o;
    }
}

extern "C" void kernel_launch(void* const* d_in, const int* in_sizes, int n_in,
                              void* d_out, int out_size)
{
    const float* user  = (const float*)d_in[0];
    const float* item  = (const float*)d_in[1];
    const int*   rows  = (const int*)  d_in[2];
    const int*   cols  = (const int*)  d_in[3];
    const float* vals  = (const float*)d_in[4];
    const float* noise = (const float*)d_in[5];
    float*       out   = (float*)d_out;

    float *e0, *e1, *acc;
    int   *cnt;
    cudaGetSymbolAddress((void**)&e0,  g_e0);
    cudaGetSymbolAddress((void**)&e1,  g_e1);
    cudaGetSymbolAddress((void**)&acc, g_acc);
    cudaGetSymbolAddress((void**)&cnt, g_cnt);

    const size_t row_bytes = (size_t)EMB * sizeof(float);

    // ---- build row-sorted CSR (must be rebuilt every call; no caching) ----
    cudaMemsetAsync(cnt, 0, (size_t)N_NODES * sizeof(int));
    count_kernel  <<<(NNZ + 255) / 256, 256>>>(rows);
    scan1_kernel  <<<SCAN_BLOCKS, 256>>>();
    scan2_kernel  <<<1, 256>>>();
    scan3_kernel  <<<(N_NODES + 255) / 256, 256>>>();
    scatter_kernel<<<(NNZ + 255) / 256, 256>>>(rows, cols, vals);

    // ---- ego(0) = concat(user_emb, item_emb) ----
    cudaMemcpyAsync(e0, user, (size_t)USER_NUM * row_bytes, cudaMemcpyDeviceToDevice);
    cudaMemcpyAsync(e0 + (size_t)USER_NUM * EMB, item,
                    (size_t)ITEM_NUM * row_bytes, cudaMemcpyDeviceToDevice);

    const int fused_blocks = (N_NODES + 7) / 8;  // warp per row, 8 warps/block

    // layer 0: e0 -> e1 ; layer 1: e1 -> e0 ; layer 2: e0 -> (out only)
    spmm_fused<<<fused_blocks, 256>>>(e0, noise + 0ull * N_NODES * EMB, e1, acc, out, 0);
    spmm_fused<<<fused_blocks, 256>>>(e1, noise + 1ull * N_NODES * EMB, e0, acc, out, 1);
    spmm_fused<<<fused_blocks, 256>>>(e0, noise + 2ull * N_NODES * EMB, e1, acc, out, 2);
}

// round 3
// speedup vs baseline: 2.4023x; 1.1159x over previous
#include <cuda_runtime.h>
#include <cuda_fp16.h>

#define USER_NUM 100000
#define ITEM_NUM 50000
#define N_NODES  150000
#define NNZ      4800000
#define EMB      64
#define EPSV     0.2f
#define NORM_EPS 1e-12f

#define SCAN_TILE   1024
#define SCAN_BLOCKS ((N_NODES + SCAN_TILE - 1) / SCAN_TILE)  // 147

// ---- scratch (allocation-free) ----
__device__ alignas(16) int    g_cnt[N_NODES];
__device__ alignas(16) int    g_rowptr[N_NODES];
__device__ alignas(16) int    g_woff[N_NODES];
__device__              int   g_bsum[SCAN_BLOCKS];
__device__ alignas(16) int2   g_pack[NNZ];                    // (col, val-bits)
__device__ alignas(256) __half g_e0[(size_t)N_NODES * EMB];   // fp16 layer state
__device__ alignas(256) __half g_e1[(size_t)N_NODES * EMB];
__device__ alignas(256) float  g_acc[(size_t)N_NODES * EMB];  // fp32 running sum

// ---- counting sort: histogram ----
__global__ void __launch_bounds__(256)
count_kernel(const int* __restrict__ rows)
{
    int i = blockIdx.x * blockDim.x + threadIdx.x;
    if (i < NNZ) atomicAdd(&g_cnt[rows[i]], 1);
}

// ---- scan stage 1 ----
__global__ void __launch_bounds__(256)
scan1_kernel()
{
    __shared__ int sh[256];
    int tid  = threadIdx.x;
    int base = blockIdx.x * SCAN_TILE + tid * 4;

    int v0 = 0, v1 = 0, v2 = 0, v3 = 0;
    if (base + 3 < N_NODES) {
        int4 t = *reinterpret_cast<const int4*>(&g_cnt[base]);
        v0 = t.x; v1 = t.y; v2 = t.z; v3 = t.w;
    } else {
        if (base + 0 < N_NODES) v0 = g_cnt[base + 0];
        if (base + 1 < N_NODES) v1 = g_cnt[base + 1];
        if (base + 2 < N_NODES) v2 = g_cnt[base + 2];
        if (base + 3 < N_NODES) v3 = g_cnt[base + 3];
    }
    int s = v0 + v1 + v2 + v3;
    sh[tid] = s;
    __syncthreads();
    #pragma unroll
    for (int o = 1; o < 256; o <<= 1) {
        int t = (tid >= o) ? sh[tid - o] : 0;
        __syncthreads();
        sh[tid] += t;
        __syncthreads();
    }
    int excl = sh[tid] - s;
    if (base + 0 < N_NODES) g_rowptr[base + 0] = excl;
    excl += v0;
    if (base + 1 < N_NODES) g_rowptr[base + 1] = excl;
    excl += v1;
    if (base + 2 < N_NODES) g_rowptr[base + 2] = excl;
    excl += v2;
    if (base + 3 < N_NODES) g_rowptr[base + 3] = excl;
    if (tid == 255) g_bsum[blockIdx.x] = sh[255];
}

// ---- scan stage 2 ----
__global__ void __launch_bounds__(256)
scan2_kernel()
{
    __shared__ int sh[256];
    int tid = threadIdx.x;
    int v = (tid < SCAN_BLOCKS) ? g_bsum[tid] : 0;
    sh[tid] = v;
    __syncthreads();
    #pragma unroll
    for (int o = 1; o < 256; o <<= 1) {
        int t = (tid >= o) ? sh[tid - o] : 0;
        __syncthreads();
        sh[tid] += t;
        __syncthreads();
    }
    if (tid < SCAN_BLOCKS) g_bsum[tid] = sh[tid] - v;
}

// ---- scan stage 3 ----
__global__ void __launch_bounds__(256)
scan3_kernel()
{
    int i = blockIdx.x * blockDim.x + threadIdx.x;
    if (i < N_NODES) {
        int r = g_rowptr[i] + g_bsum[i / SCAN_TILE];
        g_rowptr[i] = r;
        g_woff[i]   = r;
    }
}

// ---- counting sort: scatter packed (col, val) ----
__global__ void __launch_bounds__(256)
scatter_kernel(const int* __restrict__ rows, const int* __restrict__ cols,
               const float* __restrict__ vals)
{
    int i = blockIdx.x * blockDim.x + threadIdx.x;
    if (i < NNZ) {
        int p = atomicAdd(&g_woff[rows[i]], 1);
        g_pack[p] = make_int2(cols[i], __float_as_int(vals[i]));
    }
}

// ---- init: ego(0) = concat(user, item) quantized to fp16 ----
__global__ void __launch_bounds__(256)
init_kernel(const float* __restrict__ user, const float* __restrict__ item,
            __half* __restrict__ e0)
{
    int i = blockIdx.x * blockDim.x + threadIdx.x;            // half2 index
    const int total = N_NODES * EMB / 2;
    if (i >= total) return;
    const int usplit = USER_NUM * EMB / 2;
    float2 v = (i < usplit)
        ? __ldg(reinterpret_cast<const float2*>(user) + i)
        : __ldg(reinterpret_cast<const float2*>(item) + (i - usplit));
    reinterpret_cast<__half2*>(e0)[i] = __float22half2_rn(v);
}

// ---- fused CSR SpMM (warp/row, fp16 gather, fp32 accum) + epilogue ----
__global__ void __launch_bounds__(256)
spmm_fused(const __half* __restrict__ x, const float* __restrict__ noise,
           __half* __restrict__ dst, float* __restrict__ acc,
           float* __restrict__ out, int k)
{
    int warp = (int)((blockIdx.x * (unsigned)blockDim.x + threadIdx.x) >> 5);
    int lane = threadIdx.x & 31;
    if (warp >= N_NODES) return;

    int start = __ldg(&g_rowptr[warp]);
    int end   = (warp + 1 < N_NODES) ? __ldg(&g_rowptr[warp + 1]) : NNZ;

    const __half2* __restrict__ xh = reinterpret_cast<const __half2*>(x);

    float sx = 0.f, sy = 0.f;
    int j = start;
    for (; j + 4 <= end; j += 4) {
        int2 p0 = __ldg(&g_pack[j + 0]);
        int2 p1 = __ldg(&g_pack[j + 1]);
        int2 p2 = __ldg(&g_pack[j + 2]);
        int2 p3 = __ldg(&g_pack[j + 3]);
        float2 a0 = __half22float2(__ldg(xh + (size_t)p0.x * 32 + lane));
        float2 a1 = __half22float2(__ldg(xh + (size_t)p1.x * 32 + lane));
        float2 a2 = __half22float2(__ldg(xh + (size_t)p2.x * 32 + lane));
        float2 a3 = __half22float2(__ldg(xh + (size_t)p3.x * 32 + lane));
        float v0 = __int_as_float(p0.y), v1 = __int_as_float(p1.y);
        float v2 = __int_as_float(p2.y), v3 = __int_as_float(p3.y);
        sx += v0 * a0.x; sy += v0 * a0.y;
        sx += v1 * a1.x; sy += v1 * a1.y;
        sx += v2 * a2.x; sy += v2 * a2.y;
        sx += v3 * a3.x; sy += v3 * a3.y;
    }
    for (; j < end; j++) {
        int2 p = __ldg(&g_pack[j]);
        float2 a = __half22float2(__ldg(xh + (size_t)p.x * 32 + lane));
        float v = __int_as_float(p.y);
        sx += v * a.x; sy += v * a.y;
    }

    // epilogue: e = s + sign(s) * l2_normalize(noise_row) * eps
    size_t base = (size_t)warp * EMB + (size_t)lane * 2;
    float2 r = __ldg(reinterpret_cast<const float2*>(noise + base));
    float ss = r.x * r.x + r.y * r.y;
    #pragma unroll
    for (int o = 16; o; o >>= 1) ss += __shfl_xor_sync(0xffffffffu, ss, o);
    float scale = EPSV / fmaxf(sqrtf(ss), NORM_EPS);

    float2 e;
    e.x = sx + (sx > 0.f ? scale * r.x : (sx < 0.f ? -scale * r.x : 0.f));
    e.y = sy + (sy > 0.f ? scale * r.y : (sy < 0.f ? -scale * r.y : 0.f));

    if (k < 2) {
        reinterpret_cast<__half2*>(dst)[(size_t)warp * 32 + lane] =
            __float22half2_rn(e);
    }
    if (k == 0) {
        *reinterpret_cast<float2*>(acc + base) = e;
    } else if (k == 1) {
        float2 a = *reinterpret_cast<const float2*>(acc + base);
        a.x += e.x; a.y += e.y;
        *reinterpret_cast<float2*>(acc + base) = a;
    } else {
        float2 a = *reinterpret_cast<const float2*>(acc + base);
        float2 o;
        o.x = (a.x + e.x) * (1.0f / 3.0f);
        o.y = (a.y + e.y) * (1.0f / 3.0f);
        *reinterpret_cast<float2*>(out + base) = o;
    }
}

extern "C" void kernel_launch(void* const* d_in, const int* in_sizes, int n_in,
                              void* d_out, int out_size)
{
    const float* user  = (const float*)d_in[0];
    const float* item  = (const float*)d_in[1];
    const int*   rows  = (const int*)  d_in[2];
    const int*   cols  = (const int*)  d_in[3];
    const float* vals  = (const float*)d_in[4];
    const float* noise = (const float*)d_in[5];
    float*       out   = (float*)d_out;

    __half *e0, *e1;
    float  *acc;
    int    *cnt;
    cudaGetSymbolAddress((void**)&e0,  g_e0);
    cudaGetSymbolAddress((void**)&e1,  g_e1);
    cudaGetSymbolAddress((void**)&acc, g_acc);
    cudaGetSymbolAddress((void**)&cnt, g_cnt);

    // ---- build row-sorted packed CSR (rebuilt every call) ----
    cudaMemsetAsync(cnt, 0, (size_t)N_NODES * sizeof(int));
    count_kernel  <<<(NNZ + 255) / 256, 256>>>(rows);
    scan1_kernel  <<<SCAN_BLOCKS, 256>>>();
    scan2_kernel  <<<1, 256>>>();
    scan3_kernel  <<<(N_NODES + 255) / 256, 256>>>();
    scatter_kernel<<<(NNZ + 255) / 256, 256>>>(rows, cols, vals);

    // ---- ego(0) = concat(user, item) in fp16 ----
    init_kernel<<<(N_NODES * EMB / 2 + 255) / 256, 256>>>(user, item, e0);

    const int fused_blocks = (N_NODES + 7) / 8;  // warp per row

    spmm_fused<<<fused_blocks, 256>>>(e0, noise + 0ull * N_NODES * EMB, e1, acc, out, 0);
    spmm_fused<<<fused_blocks, 256>>>(e1, noise + 1ull * N_NODES * EMB, e0, acc, out, 1);
    spmm_fused<<<fused_blocks, 256>>>(e0, noise + 2ull * N_NODES * EMB, e1, acc, out, 2);
}

// round 5
// speedup vs baseline: 2.5606x; 1.0659x over previous
#include <cuda_runtime.h>
#include <cuda_fp16.h>
#include <cstdint>

#define USER_NUM 100000
#define ITEM_NUM 50000
#define N_NODES  150000
#define NNZ      4800000
#define EMB      64
#define EPSV     0.2f
#define NORM_EPS 1e-12f

#define SCAN_TILE   1024
#define SCAN_BLOCKS ((N_NODES + SCAN_TILE - 1) / SCAN_TILE)  // 147

// ---- scratch (allocation-free) ----
__device__ alignas(16) int    g_cnt[N_NODES];
__device__ alignas(16) int    g_rowptr[N_NODES];
__device__ alignas(16) int    g_woff[N_NODES];
__device__              int   g_bsum[SCAN_BLOCKS];
__device__ alignas(16) int2   g_pack[NNZ];                     // (col, val-bits)
__device__ alignas(256) __half g_e0[(size_t)N_NODES * EMB];    // fp16 layer state
__device__ alignas(256) __half g_e1[(size_t)N_NODES * EMB];
__device__ alignas(256) float  g_acc[(size_t)N_NODES * EMB];   // fp32 running sum

// ---- counting sort: histogram ----
__global__ void __launch_bounds__(256)
count_kernel(const int* __restrict__ rows)
{
    int i = blockIdx.x * blockDim.x + threadIdx.x;
    if (i < NNZ) atomicAdd(&g_cnt[rows[i]], 1);
}

// ---- scan stage 1 ----
__global__ void __launch_bounds__(256)
scan1_kernel()
{
    __shared__ int sh[256];
    int tid  = threadIdx.x;
    int base = blockIdx.x * SCAN_TILE + tid * 4;

    int v0 = 0, v1 = 0, v2 = 0, v3 = 0;
    if (base + 3 < N_NODES) {
        int4 t = *reinterpret_cast<const int4*>(&g_cnt[base]);
        v0 = t.x; v1 = t.y; v2 = t.z; v3 = t.w;
    } else {
        if (base + 0 < N_NODES) v0 = g_cnt[base + 0];
        if (base + 1 < N_NODES) v1 = g_cnt[base + 1];
        if (base + 2 < N_NODES) v2 = g_cnt[base + 2];
        if (base + 3 < N_NODES) v3 = g_cnt[base + 3];
    }
    int s = v0 + v1 + v2 + v3;
    sh[tid] = s;
    __syncthreads();
    #pragma unroll
    for (int o = 1; o < 256; o <<= 1) {
        int t = (tid >= o) ? sh[tid - o] : 0;
        __syncthreads();
        sh[tid] += t;
        __syncthreads();
    }
    int excl = sh[tid] - s;
    if (base + 0 < N_NODES) g_rowptr[base + 0] = excl;
    excl += v0;
    if (base + 1 < N_NODES) g_rowptr[base + 1] = excl;
    excl += v1;
    if (base + 2 < N_NODES) g_rowptr[base + 2] = excl;
    excl += v2;
    if (base + 3 < N_NODES) g_rowptr[base + 3] = excl;
    if (tid == 255) g_bsum[blockIdx.x] = sh[255];
}

// ---- scan stage 2 ----
__global__ void __launch_bounds__(256)
scan2_kernel()
{
    __shared__ int sh[256];
    int tid = threadIdx.x;
    int v = (tid < SCAN_BLOCKS) ? g_bsum[tid] : 0;
    sh[tid] = v;
    __syncthreads();
    #pragma unroll
    for (int o = 1; o < 256; o <<= 1) {
        int t = (tid >= o) ? sh[tid - o] : 0;
        __syncthreads();
        sh[tid] += t;
        __syncthreads();
    }
    if (tid < SCAN_BLOCKS) g_bsum[tid] = sh[tid] - v;
}

// ---- scan stage 3 ----
__global__ void __launch_bounds__(256)
scan3_kernel()
{
    int i = blockIdx.x * blockDim.x + threadIdx.x;
    if (i < N_NODES) {
        int r = g_rowptr[i] + g_bsum[i / SCAN_TILE];
        g_rowptr[i] = r;
        g_woff[i]   = r;
    }
}

// ---- counting sort: scatter packed (col, val) ----
__global__ void __launch_bounds__(256)
scatter_kernel(const int* __restrict__ rows, const int* __restrict__ cols,
               const float* __restrict__ vals)
{
    int i = blockIdx.x * blockDim.x + threadIdx.x;
    if (i < NNZ) {
        int p = atomicAdd(&g_woff[rows[i]], 1);
        g_pack[p] = make_int2(cols[i], __float_as_int(vals[i]));
    }
}

// ---- init: ego(0) = concat(user, item) quantized to fp16 ----
__global__ void __launch_bounds__(256)
init_kernel(const float* __restrict__ user, const float* __restrict__ item,
            __half* __restrict__ e0)
{
    int i = blockIdx.x * blockDim.x + threadIdx.x;             // half2 index
    const int total = N_NODES * EMB / 2;
    if (i >= total) return;
    const int usplit = USER_NUM * EMB / 2;
    float2 v = (i < usplit)
        ? __ldg(reinterpret_cast<const float2*>(user) + i)
        : __ldg(reinterpret_cast<const float2*>(item) + (i - usplit));
    reinterpret_cast<__half2*>(e0)[i] = __float22half2_rn(v);
}

// gather 4 dims (8 bytes of fp16) and fma into 4 fp32 accumulators
__device__ __forceinline__ void fma4(const uint2* __restrict__ xq, int c, int l,
                                     float v, float& s0, float& s1,
                                     float& s2, float& s3)
{
    uint2 d = __ldg(xq + (size_t)c * 16 + l);
    __half2 h0 = *reinterpret_cast<__half2*>(&d.x);
    __half2 h1 = *reinterpret_cast<__half2*>(&d.y);
    float2 f0 = __half22float2(h0);
    float2 f1 = __half22float2(h1);
    s0 = fmaf(v, f0.x, s0);
    s1 = fmaf(v, f0.y, s1);
    s2 = fmaf(v, f1.x, s2);
    s3 = fmaf(v, f1.y, s3);
}

// ---- fused CSR SpMM: warp per row, two 16-lane groups each own one nnz
// stream. Each lane covers 4 embedding dims (8B fp16). Partials merged with
// shfl_xor(16). Epilogue (sign perturbation + mean accumulation) fused. ----
__global__ void __launch_bounds__(256)
spmm_fused(const __half* __restrict__ x, const float* __restrict__ noise,
           __half* __restrict__ dst, float* __restrict__ acc,
           float* __restrict__ out, int k)
{
    int warp = (int)((blockIdx.x * (unsigned)blockDim.x + threadIdx.x) >> 5);
    int lane = threadIdx.x & 31;
    if (warp >= N_NODES) return;

    int g = lane >> 4;          // nnz-stream group (0/1)
    int l = lane & 15;          // dim-group: dims [4l, 4l+4)

    int start = __ldg(&g_rowptr[warp]);
    int end   = (warp + 1 < N_NODES) ? __ldg(&g_rowptr[warp + 1]) : NNZ;

    const uint2* __restrict__ xq = reinterpret_cast<const uint2*>(x);

    float s0 = 0.f, s1 = 0.f, s2 = 0.f, s3 = 0.f;

    int idx = start + g;        // this group's nnz: start+g, start+g+2, ...
    // 2x unrolled (4 nnz per warp-iteration)
    for (; idx + 2 < end; idx += 4) {
        int2 p0 = __ldg(&g_pack[idx]);
        int2 p1 = __ldg(&g_pack[idx + 2]);
        fma4(xq, p0.x, l, __int_as_float(p0.y), s0, s1, s2, s3);
        fma4(xq, p1.x, l, __int_as_float(p1.y), s0, s1, s2, s3);
    }
    for (; idx < end; idx += 2) {
        int2 p = __ldg(&g_pack[idx]);
        fma4(xq, p.x, l, __int_as_float(p.y), s0, s1, s2, s3);
    }

    // merge the two nnz-stream groups: lane l gets full sum for dims [4l,4l+4)
    s0 += __shfl_xor_sync(0xffffffffu, s0, 16);
    s1 += __shfl_xor_sync(0xffffffffu, s1, 16);
    s2 += __shfl_xor_sync(0xffffffffu, s2, 16);
    s3 += __shfl_xor_sync(0xffffffffu, s3, 16);

    // epilogue: e = s + sign(s) * l2_normalize(noise_row) * eps
    float4 r = __ldg(reinterpret_cast<const float4*>(noise + (size_t)warp * EMB) + l);
    float ss = r.x * r.x + r.y * r.y + r.z * r.z + r.w * r.w;
    #pragma unroll
    for (int o = 8; o; o >>= 1) ss += __shfl_xor_sync(0xffffffffu, ss, o);
    float scale = EPSV / fmaxf(sqrtf(ss), NORM_EPS);

    float4 e;
    e.x = s0 + (s0 > 0.f ? scale * r.x : (s0 < 0.f ? -scale * r.x : 0.f));
    e.y = s1 + (s1 > 0.f ? scale * r.y : (s1 < 0.f ? -scale * r.y : 0.f));
    e.z = s2 + (s2 > 0.f ? scale * r.z : (s2 < 0.f ? -scale * r.z : 0.f));
    e.w = s3 + (s3 > 0.f ? scale * r.w : (s3 < 0.f ? -scale * r.w : 0.f));

    if (g != 0) return;  // lanes 16-31 hold duplicates; group 0 writes

    size_t q = (size_t)warp * 16 + l;

    if (k < 2) {
        uint2 hpack;
        __half2 h0 = __float22half2_rn(make_float2(e.x, e.y));
        __half2 h1 = __float22half2_rn(make_float2(e.z, e.w));
        hpack.x = *reinterpret_cast<unsigned int*>(&h0);
        hpack.y = *reinterpret_cast<unsigned int*>(&h1);
        reinterpret_cast<uint2*>(dst)[q] = hpack;
    }
    if (k == 0) {
        reinterpret_cast<float4*>(acc)[q] = e;
    } else if (k == 1) {
        float4 a = reinterpret_cast<const float4*>(acc)[q];
        a.x += e.x; a.y += e.y; a.z += e.z; a.w += e.w;
        reinterpret_cast<float4*>(acc)[q] = a;
    } else {
        float4 a = reinterpret_cast<const float4*>(acc)[q];
        float4 o;
        o.x = (a.x + e.x) * (1.0f / 3.0f);
        o.y = (a.y + e.y) * (1.0f / 3.0f);
        o.z = (a.z + e.z) * (1.0f / 3.0f);
        o.w = (a.w + e.w) * (1.0f / 3.0f);
        reinterpret_cast<float4*>(out)[q] = o;
    }
}

extern "C" void kernel_launch(void* const* d_in, const int* in_sizes, int n_in,
                              void* d_out, int out_size)
{
    const float* user  = (const float*)d_in[0];
    const float* item  = (const float*)d_in[1];
    const int*   rows  = (const int*)  d_in[2];
    const int*   cols  = (const int*)  d_in[3];
    const float* vals  = (const float*)d_in[4];
    const float* noise = (const float*)d_in[5];
    float*       out   = (float*)d_out;

    __half *e0, *e1;
    float  *acc;
    int    *cnt;
    cudaGetSymbolAddress((void**)&e0,  g_e0);
    cudaGetSymbolAddress((void**)&e1,  g_e1);
    cudaGetSymbolAddress((void**)&acc, g_acc);
    cudaGetSymbolAddress((void**)&cnt, g_cnt);

    // ---- build row-sorted packed CSR (rebuilt every call) ----
    cudaMemsetAsync(cnt, 0, (size_t)N_NODES * sizeof(int));
    count_kernel  <<<(NNZ + 255) / 256, 256>>>(rows);
    scan1_kernel  <<<SCAN_BLOCKS, 256>>>();
    scan2_kernel  <<<1, 256>>>();
    scan3_kernel  <<<(N_NODES + 255) / 256, 256>>>();
    scatter_kernel<<<(NNZ + 255) / 256, 256>>>(rows, cols, vals);

    // ---- ego(0) = concat(user, item) in fp16 ----
    init_kernel<<<(N_NODES * EMB / 2 + 255) / 256, 256>>>(user, item, e0);

    const int fused_blocks = (N_NODES + 7) / 8;  // warp per row

    spmm_fused<<<fused_blocks, 256>>>(e0, noise + 0ull * N_NODES * EMB, e1, acc, out, 0);
    spmm_fused<<<fused_blocks, 256>>>(e1, noise + 1ull * N_NODES * EMB, e0, acc, out, 1);
    spmm_fused<<<fused_blocks, 256>>>(e0, noise + 2ull * N_NODES * EMB, e1, acc, out, 2);
}